// round 7
// baseline (speedup 1.0000x reference)
#include <cuda_runtime.h>

#define BB    16
#define NN    4096
#define CC    64
#define KNNK  32
#define QB    256
#define NPAIRS 2048                       // all 4096 candidates resident
#define HALFP  1024                       // pairs per stream

#define F_INF  __int_as_float(0x7f800000)
#define F_NINF __int_as_float(0xff800000)
#define FULL   0xFFFFFFFFu

typedef unsigned long long ull;

// Scratch (static device globals — allowed; no runtime allocation).
__device__ int   g_idx[BB * NN * KNNK];      // 8 MB
__device__ float g_mx[BB * NN * CC];         // 16 MB
__device__ float g_mn[BB * NN * CC];         // 16 MB
__device__ float g_part[BB * NN / 8];        // 8192 block partials
__device__ float g_inv;

// ---- Blackwell packed f32x2 ops (PTX-only; min/max.f32x2 do NOT exist) ----
__device__ __forceinline__ ull fma2(ull a, ull b, ull c) {
    ull d; asm("fma.rn.f32x2 %0, %1, %2, %3;" : "=l"(d) : "l"(a), "l"(b), "l"(c));
    return d;
}
__device__ __forceinline__ ull mul2(ull a, ull b) {
    ull d; asm("mul.rn.f32x2 %0, %1, %2;" : "=l"(d) : "l"(a), "l"(b));
    return d;
}
__device__ __forceinline__ ull pk2(float lo, float hi) {
    ull r; asm("mov.b64 %0, {%1, %2};" : "=l"(r) : "f"(lo), "f"(hi));
    return r;
}
__device__ __forceinline__ void up2(ull v, float& lo, float& hi) {
    asm("mov.b64 {%0, %1}, %2;" : "=f"(lo), "=f"(hi) : "l"(v));
}

// Branchless insert of c into ascending sorted 32-reg array (drops old max).
__device__ __forceinline__ void insert32(float (&sv)[KNNK], float c) {
#pragma unroll
    for (int u = 0; u < KNNK; u++) {
        float lo = fminf(sv[u], c);
        c = fmaxf(sv[u], c);
        sv[u] = lo;
    }
}

// ---------------------------------------------------------------------------
// Kernel 1: exact 32-NN. All candidates resident in smem; 2 threads per query
// (even/odd index halves as lane pairs); per-half exact top-32 via buffered
// FMNMX insert chains + bitonic warm-up; exact union select + analytic tie
// allocation; emission by rescan of resident candidates.
// ---------------------------------------------------------------------------
__global__ void __launch_bounds__(QB) knn_kernel(const float* __restrict__ xyz) {
    // stream-interleaved pair slots: slot = 2*t + s  (s = stream, t = step)
    __shared__ ulonglong2 s_xy[NPAIRS];              // {x01, y01}  32 KB
    __shared__ ull        s_z [NPAIRS];              //  z01        16 KB

    const int b    = blockIdx.x >> 5;                // 32 blocks per batch
    const int lane = threadIdx.x & 31;
    const int warp = threadIdx.x >> 5;
    const int s    = lane & 1;                       // stream (candidate half)
    const int i    = ((blockIdx.x & 31) << 7) + (warp << 4) + (lane >> 1);
    const float* xb = xyz + (size_t)b * (3 * NN);

    // Load + pack all 4096 candidates (2048 pairs), stream-interleaved.
    for (int p = threadIdx.x; p < NPAIRS; p += QB) {
        float2 X = *(const float2*)(xb + 2 * p);
        float2 Y = *(const float2*)(xb + NN + 2 * p);
        float2 Z = *(const float2*)(xb + 2 * NN + 2 * p);
        int slot = ((p & (HALFP - 1)) << 1) | (p >> 10);
        s_xy[slot] = make_ulonglong2(pk2(X.x, X.y), pk2(Y.x, Y.y));
        s_z[slot]  = pk2(Z.x, Z.y);
    }

    const float xi = xb[i], yi = xb[NN + i], zi = xb[2 * NN + i];
    const ull AX = pk2(-2.f * xi, -2.f * xi);
    const ull AY = pk2(-2.f * yi, -2.f * yi);
    const ull AZ = pk2(-2.f * zi, -2.f * zi);
    __syncthreads();

    // d_rel = ||xj||^2 - 2 xi.xj  (ranking-equivalent to reference pd)
    auto dist2 = [&](int t) -> ull {
        int slot = (t << 1) | s;
        ulonglong2 XY = s_xy[slot];
        ull Z = s_z[slot];
        ull nn = fma2(Z, Z, fma2(XY.y, XY.y, mul2(XY.x, XY.x)));
        return fma2(AX, XY.x, fma2(AY, XY.y, fma2(AZ, Z, nn)));
    };

    float sv[KNNK];
    // ---- warm-up: first 32 candidates of this stream, bitonic sorted ----
#pragma unroll
    for (int t = 0; t < KNNK / 2; t++) {
        float d0, d1; up2(dist2(t), d0, d1);
        sv[2 * t] = d0;
        sv[2 * t + 1] = d1;
    }
#pragma unroll
    for (int k = 2; k <= KNNK; k <<= 1) {
#pragma unroll
        for (int j = k >> 1; j > 0; j >>= 1) {
#pragma unroll
            for (int u = 0; u < KNNK; u++) {
                int l = u ^ j;
                if (l > u) {
                    bool up = ((u & k) == 0);
                    float lo = fminf(sv[u], sv[l]);
                    float hi = fmaxf(sv[u], sv[l]);
                    sv[u] = up ? lo : hi;
                    sv[l] = up ? hi : lo;
                }
            }
        }
    }
    float worst = sv[KNNK - 1];

    // ---- sweep remaining pairs of this stream ----
    float b0 = F_INF, b1 = F_INF, b2 = F_INF, b3 = F_INF;
    int cnt = 0;
#pragma unroll 4
    for (int t = KNNK / 2; t < HALFP; t++) {
        float d0, d1; up2(dist2(t), d0, d1);
        bool p0 = d0 < worst;
        bool p1 = d1 < worst;
        if (p0) { b3 = b2; b2 = b1; b1 = b0; b0 = d0; cnt++; }
        if (p1) { b3 = b2; b2 = b1; b1 = b0; b0 = d1; cnt++; }
        if (__any_sync(FULL, cnt >= 3)) {
            insert32(sv, b0); insert32(sv, b1);
            insert32(sv, b2); insert32(sv, b3);
            b0 = b1 = b2 = b3 = F_INF; cnt = 0;
            worst = sv[KNNK - 1];
        }
    }
    insert32(sv, b0); insert32(sv, b1); insert32(sv, b2); insert32(sv, b3);

    // ---- merge: exact union 32nd-smallest across the lane pair ----
    float LB[KNNK];
#pragma unroll
    for (int u = 0; u < KNNK; u++) LB[u] = __shfl_xor_sync(FULL, sv[u], 1);

    float w = F_INF;
#pragma unroll
    for (int t = 0; t <= KNNK; t++) {
        float aa = (t > 0) ? sv[t - 1] : F_NINF;
        float bb = (t < KNNK) ? LB[KNNK - 1 - t] : F_NINF;
        w = fminf(w, fmaxf(aa, bb));
    }

    int lessO = 0, eqO = 0;
#pragma unroll
    for (int u = 0; u < KNNK; u++) { lessO += (sv[u] < w); eqO += (sv[u] == w); }
    int bigO = (sv[KNNK - 1] > w) ? 1 : 0;

    int lessP = __shfl_xor_sync(FULL, lessO, 1);
    int eqP   = __shfl_xor_sync(FULL, eqO, 1);
    int bigP  = __shfl_xor_sync(FULL, bigO, 1);

    // stream0 gets tie priority (its candidate indices are all lower)
    int less0 = (s == 0) ? lessO : lessP;
    int eq0   = (s == 0) ? eqO   : eqP;
    int big0  = (s == 0) ? bigO  : bigP;
    int ties  = KNNK - (lessO + lessP);
    int avail0 = big0 ? eq0 : KNNK;
    int eq_used0 = min(avail0, ties);

    int offset, budget;
    if (s == 0) { offset = 0;                budget = eq_used0; }
    else        { offset = less0 + eq_used0; budget = ties - eq_used0; }

    // ---- emission: rescan this stream's resident candidates ----
    const int base = (b * NN + i) * KNNK + offset;
    int cnt2 = 0;
#pragma unroll 4
    for (int t = 0; t < HALFP; t++) {
        float d0, d1; up2(dist2(t), d0, d1);
        int cidx = (s << 11) + (t << 1);
        bool eq0c = (d0 == w);
        if ((d0 < w) | (eq0c & (budget > 0))) {
            g_idx[base + cnt2] = cidx;
            cnt2++;
            budget -= eq0c ? 1 : 0;
        }
        bool eq1c = (d1 == w);
        if ((d1 < w) | (eq1c & (budget > 0))) {
            g_idx[base + cnt2] = cidx + 1;
            cnt2++;
            budget -= eq1c ? 1 : 0;
        }
    }
}

// ---------------------------------------------------------------------------
// Kernel 2: warp per (b,i). Lane = channel pair. Coalesced 256B row gathers.
// Produces per-channel max/min of offsets + block partial of sum(offset^2).
// ---------------------------------------------------------------------------
__global__ void __launch_bounds__(256) gather_kernel(const float* __restrict__ feats) {
    const int gw   = (blockIdx.x << 3) + (threadIdx.x >> 5);   // b*NN + i
    const int lane = threadIdx.x & 31;
    const int b = gw >> 12;
    const int i = gw & (NN - 1);
    const float* fb = feats + ((size_t)b << 18);               // b*NN*CC

    const float2 ctr = *(const float2*)(fb + i * CC + lane * 2);
    const int myid = g_idx[gw * KNNK + lane];

    float mx0 = F_NINF, mx1 = F_NINF;
    float mn0 = F_INF,  mn1 = F_INF;
    float ss = 0.f;

#pragma unroll
    for (int k = 0; k < KNNK; k++) {
        int j = __shfl_sync(FULL, myid, k);
        float2 f = *(const float2*)(fb + j * CC + lane * 2);
        float o0 = f.x - ctr.x, o1 = f.y - ctr.y;
        mx0 = fmaxf(mx0, o0); mn0 = fminf(mn0, o0);
        mx1 = fmaxf(mx1, o1); mn1 = fminf(mn1, o1);
        ss = fmaf(o0, o0, ss);
        ss = fmaf(o1, o1, ss);
    }

    const int ob = gw * CC + lane * 2;
    *(float2*)(g_mx + ob) = make_float2(mx0, mx1);
    *(float2*)(g_mn + ob) = make_float2(mn0, mn1);

#pragma unroll
    for (int off = 16; off; off >>= 1)
        ss += __shfl_xor_sync(FULL, ss, off);

    __shared__ float bs[8];
    if (lane == 0) bs[threadIdx.x >> 5] = ss;
    __syncthreads();
    if (threadIdx.x == 0) {
        g_part[blockIdx.x] = bs[0] + bs[1] + bs[2] + bs[3] +
                             bs[4] + bs[5] + bs[6] + bs[7];
    }
}

// ---------------------------------------------------------------------------
// Kernel 3: reduce partials -> g_inv = 1/(sigma + eps)
// ---------------------------------------------------------------------------
__global__ void reduce_kernel() {
    __shared__ float sm[256];
    float sacc = 0.f;
    for (int t = threadIdx.x; t < BB * NN / 8; t += 256) sacc += g_part[t];
    sm[threadIdx.x] = sacc;
    __syncthreads();
#pragma unroll
    for (int o = 128; o; o >>= 1) {
        if (threadIdx.x < o) sm[threadIdx.x] += sm[threadIdx.x + o];
        __syncthreads();
    }
    if (threadIdx.x == 0) {
        float sigma = sm[0] / (float)((long long)BB * NN * KNNK * CC);
        g_inv = 1.f / (sigma + 1e-5f);
    }
}

// ---------------------------------------------------------------------------
// Kernel 4: pooled = select(alpha>=0, max, min) * inv * alpha + beta
// (max over k commutes with the positive/negative scale)
// ---------------------------------------------------------------------------
__global__ void __launch_bounds__(256) final_kernel(const float* __restrict__ alpha,
                                                    const float* __restrict__ beta,
                                                    float* __restrict__ out) {
    const int idx = blockIdx.x * 256 + threadIdx.x;   // float2 index, 2M total
    const float inv = g_inv;
    const int c2 = idx & (CC / 2 - 1);
    const float a0 = alpha[c2 * 2], a1 = alpha[c2 * 2 + 1];
    const float b0 = beta[c2 * 2],  b1 = beta[c2 * 2 + 1];
    const float2 mx = ((const float2*)g_mx)[idx];
    const float2 mn = ((const float2*)g_mn)[idx];
    float v0 = (a0 >= 0.f) ? mx.x : mn.x;
    float v1 = (a1 >= 0.f) ? mx.y : mn.y;
    float2 r;
    r.x = fmaf(v0 * inv, a0, b0);
    r.y = fmaf(v1 * inv, a1, b1);
    ((float2*)out)[idx] = r;
}

extern "C" void kernel_launch(void* const* d_in, const int* in_sizes, int n_in,
                              void* d_out, int out_size) {
    const float* xyz   = (const float*)d_in[0];
    const float* feats = (const float*)d_in[1];
    const float* alpha = (const float*)d_in[2];
    const float* beta  = (const float*)d_in[3];
    float* out = (float*)d_out;
    (void)in_sizes; (void)n_in; (void)out_size;

    knn_kernel<<<BB * NN * 2 / QB, QB>>>(xyz);       // 512 blocks, 2 thr/query
    gather_kernel<<<BB * NN / 8, 256>>>(feats);
    reduce_kernel<<<1, 256>>>();
    final_kernel<<<BB * NN * CC / 512, 256>>>(alpha, beta, out);
}

// round 8
// speedup vs baseline: 1.1261x; 1.1261x over previous
#include <cuda_runtime.h>

#define BB    16
#define NN    4096
#define CC    64
#define KNNK  32
#define QB    128
#define NPAIRS 2048                      // all 4096 candidates resident
#define CAP   320

#define F_INF  __int_as_float(0x7f800000)
#define F_NINF __int_as_float(0xff800000)
#define FULL   0xFFFFFFFFu

typedef unsigned long long ull;

// Scratch (static device globals — allowed; no runtime allocation).
__device__ int   g_idx[BB * NN * KNNK];      // 8 MB
__device__ float g_mx[BB * NN * CC];         // 16 MB
__device__ float g_mn[BB * NN * CC];         // 16 MB
__device__ float g_part[BB * NN / 8];        // 8192 block partials
__device__ float g_inv;

// ---- Blackwell packed f32x2 ops (PTX-only; min/max.f32x2 do NOT exist) ----
__device__ __forceinline__ ull fma2(ull a, ull b, ull c) {
    ull d; asm("fma.rn.f32x2 %0, %1, %2, %3;" : "=l"(d) : "l"(a), "l"(b), "l"(c));
    return d;
}
__device__ __forceinline__ ull mul2(ull a, ull b) {
    ull d; asm("mul.rn.f32x2 %0, %1, %2;" : "=l"(d) : "l"(a), "l"(b));
    return d;
}
__device__ __forceinline__ ull pk2(float lo, float hi) {
    ull r; asm("mov.b64 %0, {%1, %2};" : "=l"(r) : "f"(lo), "f"(hi));
    return r;
}
__device__ __forceinline__ void up2(ull v, float& lo, float& hi) {
    asm("mov.b64 {%0, %1}, %2;" : "=f"(lo), "=f"(hi) : "l"(v));
}

// Branchless insert of c into ascending sorted 32-reg array (drops old max).
__device__ __forceinline__ void insert32(float (&sv)[KNNK], float c) {
#pragma unroll
    for (int u = 0; u < KNNK; u++) {
        float lo = fminf(sv[u], c);
        c = fmaxf(sv[u], c);
        sv[u] = lo;
    }
}

// ---------------------------------------------------------------------------
// Kernel 1: exact 32-NN, one thread per query. All 4096 candidates resident
// in 48 KB smem. Bitonic warm-up (first 32 candidates) seeds the sorted
// top-32; sweep uses always-predicated accept shifts (no outer vote) and a
// single flush vote per pair. Accepted candidates recorded in index order to
// a local list, replayed for emission; per-thread rescan fallback on overflow.
// ---------------------------------------------------------------------------
__global__ void __launch_bounds__(QB) knn_kernel(const float* __restrict__ xyz) {
    __shared__ ulonglong2 s_xy[NPAIRS];              // {x01, y01}  32 KB
    __shared__ ull        s_z [NPAIRS];              //  z01        16 KB

    const int b = blockIdx.x >> 5;                   // 32 blocks per batch
    const int i = ((blockIdx.x & 31) << 7) + threadIdx.x;
    const float* xb = xyz + (size_t)b * (3 * NN);

    // Load + pack all candidates.
    for (int p = threadIdx.x; p < NPAIRS; p += QB) {
        float2 X = *(const float2*)(xb + 2 * p);
        float2 Y = *(const float2*)(xb + NN + 2 * p);
        float2 Z = *(const float2*)(xb + 2 * NN + 2 * p);
        s_xy[p] = make_ulonglong2(pk2(X.x, X.y), pk2(Y.x, Y.y));
        s_z[p]  = pk2(Z.x, Z.y);
    }

    const float xi = xb[i], yi = xb[NN + i], zi = xb[2 * NN + i];
    const ull AX = pk2(-2.f * xi, -2.f * xi);
    const ull AY = pk2(-2.f * yi, -2.f * yi);
    const ull AZ = pk2(-2.f * zi, -2.f * zi);
    __syncthreads();

    // d_rel = ||xj||^2 - 2 xi.xj  (ranking-equivalent to reference pd)
    auto dist2 = [&](int p) -> ull {
        ulonglong2 XY = s_xy[p];
        ull Z = s_z[p];
        ull nn = fma2(Z, Z, fma2(XY.y, XY.y, mul2(XY.x, XY.x)));
        return fma2(AX, XY.x, fma2(AY, XY.y, fma2(AZ, Z, nn)));
    };

    float2 rec[CAP];                                 // local mem (d, idx-bits)
    int rc = 0;
    bool ofl = false;

    float sv[KNNK];
    // ---- warm-up: first 32 candidates seed sv via bitonic sort ----------
#pragma unroll
    for (int p = 0; p < KNNK / 2; p++) {
        float d0, d1; up2(dist2(p), d0, d1);
        sv[2 * p] = d0;
        sv[2 * p + 1] = d1;
        rec[rc++] = make_float2(d0, __int_as_float(2 * p));
        rec[rc++] = make_float2(d1, __int_as_float(2 * p + 1));
    }
#pragma unroll
    for (int k = 2; k <= KNNK; k <<= 1) {
#pragma unroll
        for (int j = k >> 1; j > 0; j >>= 1) {
#pragma unroll
            for (int u = 0; u < KNNK; u++) {
                int l = u ^ j;
                if (l > u) {
                    bool up = ((u & k) == 0);
                    float lo = fminf(sv[u], sv[l]);
                    float hi = fmaxf(sv[u], sv[l]);
                    sv[u] = up ? lo : hi;
                    sv[l] = up ? hi : lo;
                }
            }
        }
    }
    float worst = sv[KNNK - 1];

    // ---- sweep: predicated shifts, ONE vote per pair ---------------------
    float b0 = F_INF, b1 = F_INF, b2 = F_INF, b3 = F_INF;
    int cnt = 0;
#pragma unroll 4
    for (int p = KNNK / 2; p < NPAIRS; p++) {
        float d0, d1; up2(dist2(p), d0, d1);
        bool p0 = d0 < worst;
        bool p1 = d1 < worst;
        if (p0) {
            b3 = b2; b2 = b1; b1 = b0; b0 = d0; cnt++;
            if (rc < CAP) rec[rc++] = make_float2(d0, __int_as_float(2 * p));
            else ofl = true;
        }
        if (p1) {
            b3 = b2; b2 = b1; b1 = b0; b0 = d1; cnt++;
            if (rc < CAP) rec[rc++] = make_float2(d1, __int_as_float(2 * p + 1));
            else ofl = true;
        }
        if (__any_sync(FULL, cnt >= 3)) {
            insert32(sv, b0); insert32(sv, b1);
            insert32(sv, b2); insert32(sv, b3);
            b0 = b1 = b2 = b3 = F_INF; cnt = 0;
            worst = sv[KNNK - 1];
        }
    }
    insert32(sv, b0); insert32(sv, b1); insert32(sv, b2); insert32(sv, b3);

    const float w = sv[KNNK - 1];                    // exact 32nd smallest
    int ties = 1;                                    // emissions allowed at ==w
#pragma unroll
    for (int u = 0; u < KNNK - 1; u++) ties += (sv[u] == w);

    const int base = (b * NN + i) * KNNK;
    if (!ofl) {
        // ---- fast path: replay recorded list ----------------------------
        int cnt2 = 0;
        for (int t = 0; t < rc; t++) {
            float2 r = rec[t];
            bool lt = r.x < w;
            bool eq = (r.x == w);
            if (lt | (eq & (ties > 0))) {
                g_idx[base + cnt2] = __float_as_int(r.y);
                cnt2++;
                ties -= eq ? 1 : 0;
            }
        }
    } else {
        // ---- fallback (never expected): rescan resident candidates ------
        int cnt2 = 0;
        for (int p = 0; p < NPAIRS; p++) {
            float d0, d1; up2(dist2(p), d0, d1);
            bool lt0 = d0 < w, eq0 = (d0 == w);
            bool lt1 = d1 < w, eq1 = (d1 == w);
            if (lt0 | (eq0 & (ties > 0))) {
                g_idx[base + cnt2] = 2 * p;
                cnt2++;
                ties -= eq0 ? 1 : 0;
            }
            if (lt1 | (eq1 & (ties > 0))) {
                g_idx[base + cnt2] = 2 * p + 1;
                cnt2++;
                ties -= eq1 ? 1 : 0;
            }
        }
    }
}

// ---------------------------------------------------------------------------
// Kernel 2: warp per (b,i). Lane = channel pair. Coalesced 256B row gathers.
// Produces per-channel max/min of offsets + block partial of sum(offset^2).
// ---------------------------------------------------------------------------
__global__ void __launch_bounds__(256) gather_kernel(const float* __restrict__ feats) {
    const int gw   = (blockIdx.x << 3) + (threadIdx.x >> 5);   // b*NN + i
    const int lane = threadIdx.x & 31;
    const int b = gw >> 12;
    const int i = gw & (NN - 1);
    const float* fb = feats + ((size_t)b << 18);               // b*NN*CC

    const float2 ctr = *(const float2*)(fb + i * CC + lane * 2);
    const int myid = g_idx[gw * KNNK + lane];

    float mx0 = F_NINF, mx1 = F_NINF;
    float mn0 = F_INF,  mn1 = F_INF;
    float ss = 0.f;

#pragma unroll
    for (int k = 0; k < KNNK; k++) {
        int j = __shfl_sync(FULL, myid, k);
        float2 f = *(const float2*)(fb + j * CC + lane * 2);
        float o0 = f.x - ctr.x, o1 = f.y - ctr.y;
        mx0 = fmaxf(mx0, o0); mn0 = fminf(mn0, o0);
        mx1 = fmaxf(mx1, o1); mn1 = fminf(mn1, o1);
        ss = fmaf(o0, o0, ss);
        ss = fmaf(o1, o1, ss);
    }

    const int ob = gw * CC + lane * 2;
    *(float2*)(g_mx + ob) = make_float2(mx0, mx1);
    *(float2*)(g_mn + ob) = make_float2(mn0, mn1);

#pragma unroll
    for (int off = 16; off; off >>= 1)
        ss += __shfl_xor_sync(FULL, ss, off);

    __shared__ float bs[8];
    if (lane == 0) bs[threadIdx.x >> 5] = ss;
    __syncthreads();
    if (threadIdx.x == 0) {
        g_part[blockIdx.x] = bs[0] + bs[1] + bs[2] + bs[3] +
                             bs[4] + bs[5] + bs[6] + bs[7];
    }
}

// ---------------------------------------------------------------------------
// Kernel 3: reduce partials -> g_inv = 1/(sigma + eps)
// ---------------------------------------------------------------------------
__global__ void reduce_kernel() {
    __shared__ float sm[256];
    float sacc = 0.f;
    for (int t = threadIdx.x; t < BB * NN / 8; t += 256) sacc += g_part[t];
    sm[threadIdx.x] = sacc;
    __syncthreads();
#pragma unroll
    for (int o = 128; o; o >>= 1) {
        if (threadIdx.x < o) sm[threadIdx.x] += sm[threadIdx.x + o];
        __syncthreads();
    }
    if (threadIdx.x == 0) {
        float sigma = sm[0] / (float)((long long)BB * NN * KNNK * CC);
        g_inv = 1.f / (sigma + 1e-5f);
    }
}

// ---------------------------------------------------------------------------
// Kernel 4: pooled = select(alpha>=0, max, min) * inv * alpha + beta
// (max over k commutes with the positive/negative scale)
// ---------------------------------------------------------------------------
__global__ void __launch_bounds__(256) final_kernel(const float* __restrict__ alpha,
                                                    const float* __restrict__ beta,
                                                    float* __restrict__ out) {
    const int idx = blockIdx.x * 256 + threadIdx.x;   // float2 index, 2M total
    const float inv = g_inv;
    const int c2 = idx & (CC / 2 - 1);
    const float a0 = alpha[c2 * 2], a1 = alpha[c2 * 2 + 1];
    const float b0 = beta[c2 * 2],  b1 = beta[c2 * 2 + 1];
    const float2 mx = ((const float2*)g_mx)[idx];
    const float2 mn = ((const float2*)g_mn)[idx];
    float v0 = (a0 >= 0.f) ? mx.x : mn.x;
    float v1 = (a1 >= 0.f) ? mx.y : mn.y;
    float2 r;
    r.x = fmaf(v0 * inv, a0, b0);
    r.y = fmaf(v1 * inv, a1, b1);
    ((float2*)out)[idx] = r;
}

extern "C" void kernel_launch(void* const* d_in, const int* in_sizes, int n_in,
                              void* d_out, int out_size) {
    const float* xyz   = (const float*)d_in[0];
    const float* feats = (const float*)d_in[1];
    const float* alpha = (const float*)d_in[2];
    const float* beta  = (const float*)d_in[3];
    float* out = (float*)d_out;
    (void)in_sizes; (void)n_in; (void)out_size;

    knn_kernel<<<BB * NN / QB, QB>>>(xyz);
    gather_kernel<<<BB * NN / 8, 256>>>(feats);
    reduce_kernel<<<1, 256>>>();
    final_kernel<<<BB * NN * CC / 512, 256>>>(alpha, beta, out);
}